// round 6
// baseline (speedup 1.0000x reference)
#include <cuda_runtime.h>
#include <cstdint>

#define ND 128
#define ED 64
#define HID 256
#define NMAX 100000
#define TM 64          // rows per CTA
#define NTHREADS 256   // precompute kernel
#define ETHREADS 512   // edge kernel

typedef unsigned long long ull;

__device__ __forceinline__ ull pack2(float lo, float hi) {
    ull r; asm("mov.b64 %0, {%1, %2};" : "=l"(r) : "f"(lo), "f"(hi)); return r;
}
__device__ __forceinline__ void fma2(ull &d, ull a, ull b) {
    asm("fma.rn.f32x2 %0, %1, %2, %0;" : "+l"(d) : "l"(a), "l"(b));
}
__device__ __forceinline__ ull add2(ull a, ull b) {
    ull r; asm("add.rn.f32x2 %0, %1, %2;" : "=l"(r) : "l"(a), "l"(b)); return r;
}
__device__ __forceinline__ float2 unpack2(ull v) {
    float2 f; asm("mov.b64 {%0, %1}, %2;" : "=f"(f.x), "=f"(f.y) : "l"(v)); return f;
}

// Per-node precomputed partials: Pa = x@W1a + b1, Pb = x@W1b
__device__ __align__(16) float g_Pa[(size_t)NMAX * HID];
__device__ __align__(16) float g_Pb[(size_t)NMAX * HID];
// W2 transposed, 4 k-chunks of 64, row stride 68 floats (conflict-free LDS.128)
#define W2T_STRIDE 68
#define W2T_CHUNK  (ED * W2T_STRIDE)       // 4352 floats
__device__ __align__(16) float g_W2t[4 * W2T_CHUNK];

extern __shared__ float smem[];

// ===================== Prep: transpose W2 into padded chunks ====================
__global__ void prep_w2t(const float* __restrict__ w2) {
    int i = blockIdx.x * blockDim.x + threadIdx.x;
    if (i < 4 * ED * 64) {
        int kk = i & 63, c = (i >> 6) & 63, ch = i >> 12;
        g_W2t[ch * W2T_CHUNK + c * W2T_STRIDE + kk] = w2[(ch * 64 + kk) * ED + c];
    }
}

// ===================== Kernel 1: node-level precompute ==========================
__global__ __launch_bounds__(NTHREADS, 2) void precompute_kernel(
    const float* __restrict__ x,
    const float* __restrict__ w1, const float* __restrict__ b1, int N)
{
    float* Xs = smem;              // [64][128]
    float* Bs = smem + TM * ND;    // [64][256]

    const int tid = threadIdx.x;
    const int tx  = tid & 31;
    const int ty  = tid >> 5;
    const int r0  = ty * 8;
    const int m0  = blockIdx.x * TM;
    const int half = blockIdx.y;

    int node[8];
    #pragma unroll
    for (int r = 0; r < 8; r++) {
        node[r] = min(m0 + r0 + r, N - 1);
        ((float4*)(Xs + (r0 + r) * ND))[tx] =
            ((const float4*)(x + (size_t)node[r] * ND))[tx];
    }

    ull acc[8][4];
    if (half == 0) {
        ull bv[4];
        #pragma unroll
        for (int j = 0; j < 4; j++) {
            float2 b = ((const float2*)b1)[tx + 32 * j];
            bv[j] = pack2(b.x, b.y);
        }
        #pragma unroll
        for (int i = 0; i < 8; i++)
            #pragma unroll
            for (int j = 0; j < 4; j++) acc[i][j] = bv[j];
    } else {
        #pragma unroll
        for (int i = 0; i < 8; i++)
            #pragma unroll
            for (int j = 0; j < 4; j++) acc[i][j] = 0ull;
    }

    for (int kt = 0; kt < ND; kt += 64) {
        __syncthreads();
        const float4* wf4 = (const float4*)(w1 + (size_t)(half * ND + kt) * HID);
        #pragma unroll
        for (int it = 0; it < 16; it++) {
            int q = tid + it * NTHREADS;
            ((float4*)Bs)[q] = wf4[q];
        }
        __syncthreads();
        #pragma unroll 4
        for (int kk4 = 0; kk4 < 64; kk4 += 4) {
            float4 a4[8];
            #pragma unroll
            for (int i = 0; i < 8; i++)
                a4[i] = *(const float4*)(Xs + (r0 + i) * ND + kt + kk4);
            #pragma unroll
            for (int kq = 0; kq < 4; kq++) {
                const ull* Br = (const ull*)(Bs + (kk4 + kq) * HID) + tx;
                ull b0 = Br[0], b1r = Br[32], b2r = Br[64], b3r = Br[96];
                #pragma unroll
                for (int i = 0; i < 8; i++) {
                    float a = (&a4[i].x)[kq];
                    ull aa = pack2(a, a);
                    fma2(acc[i][0], aa, b0);
                    fma2(acc[i][1], aa, b1r);
                    fma2(acc[i][2], aa, b2r);
                    fma2(acc[i][3], aa, b3r);
                }
            }
        }
    }

    float* P = half ? g_Pb : g_Pa;
    #pragma unroll
    for (int i = 0; i < 8; i++) {
        float2* dst = (float2*)(P + (size_t)node[i] * HID);
        #pragma unroll
        for (int j = 0; j < 4; j++)
            dst[tx + 32 * j] = unpack2(acc[i][j]);
    }
}

// ===================== Kernel 2: per-edge fused MLP + LN ========================
// SMEM: Es [64][64] | Ws [64][256] (W1c then h) | Cs [64][68] (W2t chunk)
#define ES_OFF 0
#define WS_OFF (TM * ED)
#define CS_OFF (TM * ED + TM * HID)
#define EDGE_SMEM ((TM * ED + TM * HID + ED * W2T_STRIDE) * 4)   // 99328 B

__global__ __launch_bounds__(ETHREADS, 2) void edge_kernel(
    const int* __restrict__ ei32,
    const float* __restrict__ edge_attr,
    const float* __restrict__ w1,       // rows [256,320) = W1c
    const float* __restrict__ b2,
    const float* __restrict__ ln_w, const float* __restrict__ ln_b,
    float* __restrict__ out, int E, int N)
{
    float* Es = smem + ES_OFF;
    float* Ws = smem + WS_OFF;
    float* Cs = smem + CS_OFF;

    const int tid = threadIdx.x;
    const int tx  = tid & 31;
    const int warp = tid >> 5;          // 0..15
    const int r0  = warp * 4;           // warp owns rows r0..r0+3
    const int e0  = blockIdx.x * TM;

    // int64/int32 detection
    unsigned oddbits = 0;
    #pragma unroll
    for (int k = 0; k < 16; k++) oddbits |= (unsigned)ei32[2 * k + 1];
    const int step = (oddbits == 0) ? 2 : 1;

    // W1c tile -> Ws  (4096 float4, 8 per thread)
    {
        const float4* wf4 = (const float4*)(w1 + (size_t)(2 * ND) * HID);
        #pragma unroll
        for (int it = 0; it < 8; it++) {
            int q = tid + it * ETHREADS;
            ((float4*)Ws)[q] = wf4[q];
        }
    }

    // per-row: gather Pa[dst]+Pb[src] into acc; load edge_attr rows into Es
    ull acc[4][4];
    int erow[4];
    #pragma unroll
    for (int i = 0; i < 4; i++) {
        int e = min(e0 + r0 + i, E - 1);
        erow[i] = e;
        int ss = ei32[(size_t)step * e];
        int ds = ei32[(size_t)step * (E + e)];
        ss = min(max(ss, 0), N - 1);
        ds = min(max(ds, 0), N - 1);
        const ull* pa = (const ull*)(g_Pa + (size_t)ds * HID) + tx;
        const ull* pb = (const ull*)(g_Pb + (size_t)ss * HID) + tx;
        #pragma unroll
        for (int j = 0; j < 4; j++)
            acc[i][j] = add2(pa[32 * j], pb[32 * j]);
        if (tx < 16)
            ((float4*)(Es + (r0 + i) * ED))[tx] =
                ((const float4*)(edge_attr + (size_t)e * ED))[tx];
    }
    __syncthreads();   // Ws (W1c) + Es visible

    // -------- GEMM1 remainder: acc += ea @ W1c  (K = 64) --------
    #pragma unroll 4
    for (int kk2 = 0; kk2 < ED; kk2 += 2) {
        ull a2[4];
        #pragma unroll
        for (int i = 0; i < 4; i++)
            a2[i] = *(const ull*)(Es + (r0 + i) * ED + kk2);
        #pragma unroll
        for (int kq = 0; kq < 2; kq++) {
            const ull* Br = (const ull*)(Ws + (kk2 + kq) * HID) + tx;
            ull b0 = Br[0], b1r = Br[32], b2r = Br[64], b3r = Br[96];
            #pragma unroll
            for (int i = 0; i < 4; i++) {
                float2 ap = unpack2(a2[i]);
                float a = kq ? ap.y : ap.x;
                ull aa = pack2(a, a);
                fma2(acc[i][0], aa, b0);
                fma2(acc[i][1], aa, b1r);
                fma2(acc[i][2], aa, b2r);
                fma2(acc[i][3], aa, b3r);
            }
        }
    }
    __syncthreads();   // all W1c reads done; Ws becomes h

    // h = relu(acc) -> Ws (own rows only)
    #pragma unroll
    for (int i = 0; i < 4; i++) {
        float* hr = Ws + (r0 + i) * HID;
        #pragma unroll
        for (int j = 0; j < 4; j++) {
            float2 v = unpack2(acc[i][j]);
            v.x = fmaxf(v.x, 0.f);
            v.y = fmaxf(v.y, 0.f);
            ((float2*)hr)[tx + 32 * j] = v;
        }
    }
    // no sync needed: GEMM2 reads only this warp's h rows

    // -------- GEMM2: delta = h @ W2, k-pair packed (even/odd partial sums) --------
    ull acc2[4][2];
    #pragma unroll
    for (int i = 0; i < 4; i++) { acc2[i][0] = 0ull; acc2[i][1] = 0ull; }

    for (int ch = 0; ch < 4; ch++) {
        __syncthreads();   // previous Cs reads done
        {
            const float4* src = (const float4*)(g_W2t + ch * W2T_CHUNK);
            float4* dst = (float4*)Cs;
            for (int q = tid; q < W2T_CHUNK / 4; q += ETHREADS)
                dst[q] = src[q];
        }
        __syncthreads();
        #pragma unroll 4
        for (int kk4 = 0; kk4 < 64; kk4 += 4) {
            ull ha[4][2], bb[2][2];
            #pragma unroll
            for (int i = 0; i < 4; i++) {
                float4 v = *(const float4*)(Ws + (r0 + i) * HID + ch * 64 + kk4);
                ha[i][0] = pack2(v.x, v.y);
                ha[i][1] = pack2(v.z, v.w);
            }
            #pragma unroll
            for (int j = 0; j < 2; j++) {
                float4 v = *(const float4*)(Cs + (tx + 32 * j) * W2T_STRIDE + kk4);
                bb[j][0] = pack2(v.x, v.y);
                bb[j][1] = pack2(v.z, v.w);
            }
            #pragma unroll
            for (int i = 0; i < 4; i++)
                #pragma unroll
                for (int j = 0; j < 2; j++) {
                    fma2(acc2[i][j], ha[i][0], bb[j][0]);
                    fma2(acc2[i][j], ha[i][1], bb[j][1]);
                }
        }
    }

    // -------- Epilogue: residual + LayerNorm(64) + affine --------
    float b2a = __ldg(b2 + tx),        b2b = __ldg(b2 + tx + 32);
    float lwa = __ldg(ln_w + tx),      lwb = __ldg(ln_w + tx + 32);
    float lba = __ldg(ln_b + tx),      lbb = __ldg(ln_b + tx + 32);

    #pragma unroll
    for (int i = 0; i < 4; i++) {
        float2 p0 = unpack2(acc2[i][0]);
        float2 p1 = unpack2(acc2[i][1]);
        float d0 = p0.x + p0.y;        // sum even/odd partials
        float d1 = p1.x + p1.y;
        float v0 = Es[(r0 + i) * ED + tx]      + d0 + b2a;
        float v1 = Es[(r0 + i) * ED + tx + 32] + d1 + b2b;
        float s = v0 + v1;
        float q = v0 * v0 + v1 * v1;
        #pragma unroll
        for (int off = 16; off > 0; off >>= 1) {
            s += __shfl_xor_sync(0xffffffffu, s, off);
            q += __shfl_xor_sync(0xffffffffu, q, off);
        }
        float mean = s * 0.015625f;
        float var  = q * 0.015625f - mean * mean;
        float inv  = rsqrtf(var + 1e-5f);
        if (e0 + r0 + i < E) {
            float* op = out + (size_t)erow[i] * ED;
            op[tx]      = (v0 - mean) * inv * lwa + lba;
            op[tx + 32] = (v1 - mean) * inv * lwb + lbb;
        }
    }
}

extern "C" void kernel_launch(void* const* d_in, const int* in_sizes, int n_in,
                              void* d_out, int out_size) {
    const float* x   = (const float*)d_in[0];
    const int*   ei  = (const int*)d_in[1];
    const float* ea  = (const float*)d_in[2];
    const float* w1  = (const float*)d_in[3];
    const float* b1  = (const float*)d_in[4];
    const float* w2  = (const float*)d_in[5];
    const float* b2  = (const float*)d_in[6];
    const float* lnw = (const float*)d_in[7];
    const float* lnb = (const float*)d_in[8];
    float* out = (float*)d_out;

    int E = in_sizes[1] / 2;
    int N = in_sizes[0] / ND;

    static int init_done = 0;
    int smem_pre = (TM * ND + TM * HID) * (int)sizeof(float);   // 98304
    if (!init_done) {
        cudaFuncSetAttribute(precompute_kernel,
                             cudaFuncAttributeMaxDynamicSharedMemorySize, smem_pre);
        cudaFuncSetAttribute(edge_kernel,
                             cudaFuncAttributeMaxDynamicSharedMemorySize, EDGE_SMEM);
        init_done = 1;
    }

    prep_w2t<<<(4 * ED * 64 + 255) / 256, 256>>>(w2);

    dim3 pgrid((N + TM - 1) / TM, 2);
    precompute_kernel<<<pgrid, NTHREADS, smem_pre>>>(x, w1, b1, N);

    int egrid = (E + TM - 1) / TM;
    edge_kernel<<<egrid, ETHREADS, EDGE_SMEM>>>(
        ei, ea, w1, b2, lnw, lnb, out, E, N);
}

// round 7
// speedup vs baseline: 1.1288x; 1.1288x over previous
#include <cuda_runtime.h>
#include <cuda_bf16.h>
#include <cstdint>

#define ND 128
#define ED 64
#define HID 256
#define NMAX 100000
#define TM 64          // edges per CTA
#define NTHREADS 256

typedef unsigned long long ull;

// ---------------- fp32x2 helpers (precompute kernel) ----------------
__device__ __forceinline__ ull pack2(float lo, float hi) {
    ull r; asm("mov.b64 %0, {%1, %2};" : "=l"(r) : "f"(lo), "f"(hi)); return r;
}
__device__ __forceinline__ void fma2(ull &d, ull a, ull b) {
    asm("fma.rn.f32x2 %0, %1, %2, %0;" : "+l"(d) : "l"(a), "l"(b));
}
__device__ __forceinline__ float2 unpack2(ull v) {
    float2 f; asm("mov.b64 {%0, %1}, %2;" : "=f"(f.x), "=f"(f.y) : "l"(v)); return f;
}

// ---------------- HMMA helpers ----------------
__device__ __forceinline__ uint32_t smem_u32(const void* p) {
    uint32_t a;
    asm("{ .reg .u64 t; cvta.to.shared.u64 t, %1; cvt.u32.u64 %0, t; }" : "=r"(a) : "l"(p));
    return a;
}
__device__ __forceinline__ void ldsm4(uint32_t* r, uint32_t addr) {
    asm volatile("ldmatrix.sync.aligned.m8n8.x4.shared.b16 {%0,%1,%2,%3}, [%4];"
                 : "=r"(r[0]), "=r"(r[1]), "=r"(r[2]), "=r"(r[3]) : "r"(addr));
}
__device__ __forceinline__ void ldsm4t(uint32_t* r, uint32_t addr) {
    asm volatile("ldmatrix.sync.aligned.m8n8.x4.trans.shared.b16 {%0,%1,%2,%3}, [%4];"
                 : "=r"(r[0]), "=r"(r[1]), "=r"(r[2]), "=r"(r[3]) : "r"(addr));
}
__device__ __forceinline__ void mma16816(float* c, const uint32_t* a,
                                         uint32_t b0, uint32_t b1) {
    asm volatile(
        "mma.sync.aligned.m16n8k16.row.col.f32.bf16.bf16.f32 "
        "{%0,%1,%2,%3}, {%4,%5,%6,%7}, {%8,%9}, {%0,%1,%2,%3};"
        : "+f"(c[0]), "+f"(c[1]), "+f"(c[2]), "+f"(c[3])
        : "r"(a[0]), "r"(a[1]), "r"(a[2]), "r"(a[3]), "r"(b0), "r"(b1));
}
// pack two floats to bf16x2: low 16 bits = v0 (lower address), high = v1
__device__ __forceinline__ uint32_t packbf(float v0, float v1) {
    uint32_t r; asm("cvt.rn.bf16x2.f32 %0, %1, %2;" : "=r"(r) : "f"(v1), "f"(v0));
    return r;
}
__device__ __forceinline__ void split_bf(float v, float& hf, float& lf) {
    __nv_bfloat16 h = __float2bfloat16(v);
    hf = __bfloat162float(h);
    lf = v - hf;
}

// ---------------- device-global scratch ----------------
__device__ __align__(16) float g_Pa[(size_t)NMAX * HID];   // x@W1a + b1
__device__ __align__(16) float g_Pb[(size_t)NMAX * HID];   // x@W1b
// W1c bf16 image: [hi|lo], each [64][264] (stride 264, pads unread)
__device__ __align__(16) __nv_bfloat16 g_W1cimg[2 * 64 * 264];
// W2 bf16 image: 4 k-chunks, each [hi|lo][64][72]
__device__ __align__(16) __nv_bfloat16 g_W2img[4][2 * 64 * 72];

// ---------------- SMEM layout (edge kernel), byte offsets ----------------
#define EA_HI   0                       // [64][72] bf16 = 9216
#define EA_LO   9216                    // (EA region doubles as fp32 LN buf [64][68])
#define WH_HI   18432                   // [64][264] bf16 = 33792 (W1c, then h)
#define WH_LO   (18432 + 33792)         // 52224
#define W2C_HI  86016                   // [64][72] bf16 = 9216 (chunk)
#define W2C_LO  95232
#define IDX_OFF 104448                  // ds[64], ss[64] ints
#define EDGE_SMEM (104448 + 512)        // 104960 B -> 2 CTAs/SM

extern __shared__ float smem[];

// ===================== Prep: split weights into bf16 hi/lo images ==============
__global__ void prep_weights(const float* __restrict__ w1, const float* __restrict__ w2) {
    int i = blockIdx.x * blockDim.x + threadIdx.x;
    if (i < 64 * HID) {                         // W1c rows 256..319 of w1
        int k = i / HID, n = i % HID;
        float v = w1[(size_t)(2 * ND + k) * HID + n];
        float hf, lf; split_bf(v, hf, lf);
        g_W1cimg[k * 264 + n]            = __float2bfloat16(hf);
        g_W1cimg[64 * 264 + k * 264 + n] = __float2bfloat16(lf);
    } else {
        int j = i - 64 * HID;
        if (j < HID * ED) {                     // W2 [256][64]
            int k = j / ED, n = j % ED;
            float v = w2[(size_t)k * ED + n];
            float hf, lf; split_bf(v, hf, lf);
            int ch = k >> 6, kk = k & 63;
            g_W2img[ch][kk * 72 + n]           = __float2bfloat16(hf);
            g_W2img[ch][64 * 72 + kk * 72 + n] = __float2bfloat16(lf);
        }
    }
}

// ===================== Kernel 1: node-level precompute (FFMA2, proven) =========
__global__ __launch_bounds__(NTHREADS, 2) void precompute_kernel(
    const float* __restrict__ x,
    const float* __restrict__ w1, const float* __restrict__ b1, int N)
{
    float* Xs = smem;              // [64][128]
    float* Bs = smem + TM * ND;    // [64][256]

    const int tid = threadIdx.x;
    const int tx  = tid & 31;
    const int ty  = tid >> 5;
    const int r0  = ty * 8;
    const int m0  = blockIdx.x * TM;
    const int half = blockIdx.y;

    int node[8];
    #pragma unroll
    for (int r = 0; r < 8; r++) {
        node[r] = min(m0 + r0 + r, N - 1);
        ((float4*)(Xs + (r0 + r) * ND))[tx] =
            ((const float4*)(x + (size_t)node[r] * ND))[tx];
    }

    ull acc[8][4];
    if (half == 0) {
        ull bv[4];
        #pragma unroll
        for (int j = 0; j < 4; j++) {
            float2 b = ((const float2*)b1)[tx + 32 * j];
            bv[j] = pack2(b.x, b.y);
        }
        #pragma unroll
        for (int i = 0; i < 8; i++)
            #pragma unroll
            for (int j = 0; j < 4; j++) acc[i][j] = bv[j];
    } else {
        #pragma unroll
        for (int i = 0; i < 8; i++)
            #pragma unroll
            for (int j = 0; j < 4; j++) acc[i][j] = 0ull;
    }

    for (int kt = 0; kt < ND; kt += 64) {
        __syncthreads();
        const float4* wf4 = (const float4*)(w1 + (size_t)(half * ND + kt) * HID);
        #pragma unroll
        for (int it = 0; it < 16; it++) {
            int q = tid + it * NTHREADS;
            ((float4*)Bs)[q] = wf4[q];
        }
        __syncthreads();
        #pragma unroll 4
        for (int kk4 = 0; kk4 < 64; kk4 += 4) {
            float4 a4[8];
            #pragma unroll
            for (int i = 0; i < 8; i++)
                a4[i] = *(const float4*)(Xs + (r0 + i) * ND + kt + kk4);
            #pragma unroll
            for (int kq = 0; kq < 4; kq++) {
                const ull* Br = (const ull*)(Bs + (kk4 + kq) * HID) + tx;
                ull b0 = Br[0], b1r = Br[32], b2r = Br[64], b3r = Br[96];
                #pragma unroll
                for (int i = 0; i < 8; i++) {
                    float a = (&a4[i].x)[kq];
                    ull aa = pack2(a, a);
                    fma2(acc[i][0], aa, b0);
                    fma2(acc[i][1], aa, b1r);
                    fma2(acc[i][2], aa, b2r);
                    fma2(acc[i][3], aa, b3r);
                }
            }
        }
    }

    float* P = half ? g_Pb : g_Pa;
    #pragma unroll
    for (int i = 0; i < 8; i++) {
        float2* dst = (float2*)(P + (size_t)node[i] * HID);
        #pragma unroll
        for (int j = 0; j < 4; j++)
            dst[tx + 32 * j] = unpack2(acc[i][j]);
    }
}

// ===================== Kernel 2: per-edge HMMA bf16x3 ==========================
__global__ __launch_bounds__(NTHREADS, 2) void edge_tc_kernel(
    const int* __restrict__ ei32,
    const float* __restrict__ edge_attr,
    const float* __restrict__ b2,
    const float* __restrict__ ln_w, const float* __restrict__ ln_b,
    float* __restrict__ out, int E, int N)
{
    unsigned char* sm = (unsigned char*)smem;
    const uint32_t sb = smem_u32(sm);
    const int tid  = threadIdx.x;
    const int lane = tid & 31;
    const int warp = tid >> 5;        // 0..7
    const int mg   = warp & 3;        // row group (16 rows)
    const int ng   = warp >> 2;       // col group
    const int e0   = blockIdx.x * TM;

    // ---- index load (int64/int32 detect) ----
    unsigned oddbits = 0;
    #pragma unroll
    for (int k = 0; k < 16; k++) oddbits |= (unsigned)ei32[2 * k + 1];
    const int step = (oddbits == 0) ? 2 : 1;
    if (tid < TM) {
        int e = min(e0 + tid, E - 1);
        int ss = ei32[(size_t)step * e];
        int ds = ei32[(size_t)step * (E + e)];
        ((int*)(sm + IDX_OFF))[tid]      = min(max(ds, 0), N - 1);
        ((int*)(sm + IDX_OFF))[64 + tid] = min(max(ss, 0), N - 1);
    }

    // ---- edge_attr -> ea bf16 hi/lo tiles ----
    {
        int r = tid >> 2, cq = (tid & 3) * 16;         // row, col base (16 cols)
        int e = min(e0 + r, E - 1);
        const float4* src = (const float4*)(edge_attr + (size_t)e * ED + cq);
        #pragma unroll
        for (int q = 0; q < 4; q++) {
            float4 v = src[q];
            float h0,l0,h1,l1,h2,l2,h3,l3;
            split_bf(v.x,h0,l0); split_bf(v.y,h1,l1);
            split_bf(v.z,h2,l2); split_bf(v.w,h3,l3);
            int ob = r * 144 + (cq + q * 4) * 2;
            *(uint2*)(sm + EA_HI + ob) = make_uint2(packbf(h0,h1), packbf(h2,h3));
            *(uint2*)(sm + EA_LO + ob) = make_uint2(packbf(l0,l1), packbf(l2,l3));
        }
    }

    // ---- copy W1c image (67584 B = 4224 float4) ----
    {
        const float4* src = (const float4*)g_W1cimg;
        float4* dst = (float4*)(sm + WH_HI);
        for (int q = tid; q < 4224; q += NTHREADS) dst[q] = src[q];
    }
    __syncthreads();

    const int* dsA = (const int*)(sm + IDX_OFF);
    const int* ssA = dsA + 64;
    const int rlo = 16 * mg + (lane >> 2);
    const int rhi = rlo + 8;
    const int cq2 = 2 * (lane & 3);

    // ---- GEMM1: c1 = Pa[dst]+Pb[src] (fp32) + ea @ W1c (bf16x3) ----
    float c1[16][4];
    {
        int ds_l = dsA[rlo], ss_l = ssA[rlo];
        int ds_h = dsA[rhi], ss_h = ssA[rhi];
        const float* paL = g_Pa + (size_t)ds_l * HID;
        const float* pbL = g_Pb + (size_t)ss_l * HID;
        const float* paH = g_Pa + (size_t)ds_h * HID;
        const float* pbH = g_Pb + (size_t)ss_h * HID;
        #pragma unroll
        for (int j = 0; j < 16; j++) {
            int col = 128 * ng + 8 * j + cq2;
            float2 a = *(const float2*)(paL + col);
            float2 b = *(const float2*)(pbL + col);
            float2 c = *(const float2*)(paH + col);
            float2 d = *(const float2*)(pbH + col);
            c1[j][0] = a.x + b.x; c1[j][1] = a.y + b.y;
            c1[j][2] = c.x + d.x; c1[j][3] = c.y + d.y;
        }
    }
    {
        const uint32_t aBase = sb + EA_HI + (16*mg + (lane & 15)) * 144 + (lane >> 4) * 16;
        #pragma unroll
        for (int k16 = 0; k16 < 4; k16++) {
            uint32_t ah[4], al[4];
            ldsm4(ah, aBase + k16 * 32);
            ldsm4(al, aBase + k16 * 32 + (EA_LO - EA_HI));
            #pragma unroll
            for (int nt = 0; nt < 8; nt++) {
                uint32_t bAddr = sb + WH_HI + (k16*16 + (lane & 15)) * 528
                               + (128*ng + 16*nt) * 2 + (lane >> 4) * 16;
                uint32_t bh[4], bl[4];
                ldsm4t(bh, bAddr);
                ldsm4t(bl, bAddr + (WH_LO - WH_HI));
                mma16816(c1[2*nt],   ah, bh[0], bh[1]);
                mma16816(c1[2*nt],   al, bh[0], bh[1]);
                mma16816(c1[2*nt],   ah, bl[0], bl[1]);
                mma16816(c1[2*nt+1], ah, bh[2], bh[3]);
                mma16816(c1[2*nt+1], al, bh[2], bh[3]);
                mma16816(c1[2*nt+1], ah, bl[2], bl[3]);
            }
        }
    }
    __syncthreads();   // all W1c reads done; WH region becomes h

    // ---- h = relu(c1) -> bf16 hi/lo into WH ----
    #pragma unroll
    for (int j = 0; j < 16; j++) {
        int cb = (128 * ng + 8 * j + cq2) * 2;
        float v0 = fmaxf(c1[j][0], 0.f), v1 = fmaxf(c1[j][1], 0.f);
        float v2 = fmaxf(c1[j][2], 0.f), v3 = fmaxf(c1[j][3], 0.f);
        float h0,l0,h1,l1,h2,l2,h3,l3;
        split_bf(v0,h0,l0); split_bf(v1,h1,l1);
        split_bf(v2,h2,l2); split_bf(v3,h3,l3);
        *(uint32_t*)(sm + WH_HI + rlo * 528 + cb) = packbf(h0, h1);
        *(uint32_t*)(sm + WH_LO + rlo * 528 + cb) = packbf(l0, l1);
        *(uint32_t*)(sm + WH_HI + rhi * 528 + cb) = packbf(h2, h3);
        *(uint32_t*)(sm + WH_LO + rhi * 528 + cb) = packbf(l2, l3);
    }

    // ---- GEMM2: c2 = h @ W2 (bf16x3), warp = (mg rows16, ng cols32) ----
    float c2[4][4];
    #pragma unroll
    for (int j = 0; j < 4; j++)
        #pragma unroll
        for (int q = 0; q < 4; q++) c2[j][q] = 0.f;

    for (int ch = 0; ch < 4; ch++) {
        __syncthreads();
        {
            const float4* src = (const float4*)g_W2img[ch];
            float4* dst = (float4*)(sm + W2C_HI);
            for (int q = tid; q < 1152; q += NTHREADS) dst[q] = src[q];
        }
        __syncthreads();
        #pragma unroll
        for (int k16 = 0; k16 < 4; k16++) {
            uint32_t aAddr = sb + WH_HI + (16*mg + (lane & 15)) * 528
                           + (64*ch + 16*k16) * 2 + (lane >> 4) * 16;
            uint32_t ah[4], al[4];
            ldsm4(ah, aAddr);
            ldsm4(al, aAddr + (WH_LO - WH_HI));
            #pragma unroll
            for (int nt = 0; nt < 2; nt++) {
                uint32_t bAddr = sb + W2C_HI + (k16*16 + (lane & 15)) * 144
                               + (32*ng + 16*nt) * 2 + (lane >> 4) * 16;
                uint32_t bh[4], bl[4];
                ldsm4t(bh, bAddr);
                ldsm4t(bl, bAddr + (W2C_LO - W2C_HI));
                mma16816(c2[2*nt],   ah, bh[0], bh[1]);
                mma16816(c2[2*nt],   al, bh[0], bh[1]);
                mma16816(c2[2*nt],   ah, bl[0], bl[1]);
                mma16816(c2[2*nt+1], ah, bh[2], bh[3]);
                mma16816(c2[2*nt+1], al, bh[2], bh[3]);
                mma16816(c2[2*nt+1], ah, bl[2], bl[3]);
            }
        }
    }
    __syncthreads();   // W2 chunk reads done; EA region becomes LN buffer

    // ---- stage delta + b2 into fp32 buffer [64][68] ----
    {
        float* buf = (float*)(sm + EA_HI);
        #pragma unroll
        for (int j = 0; j < 4; j++) {
            int col = 32 * ng + 8 * j + cq2;
            float bb0 = __ldg(b2 + col), bb1 = __ldg(b2 + col + 1);
            *(float2*)(buf + rlo * 68 + col) = make_float2(c2[j][0] + bb0, c2[j][1] + bb1);
            *(float2*)(buf + rhi * 68 + col) = make_float2(c2[j][2] + bb0, c2[j][3] + bb1);
        }
    }
    __syncthreads();

    // ---- LayerNorm: warp w rows 8w..8w+7; quad per row, 16 cols per lane ----
    {
        const float* buf = (const float*)(sm + EA_HI);
        int r = 8 * warp + (lane >> 2);
        int cb = (lane & 3) * 16;
        int e = e0 + r;
        int ec = min(e, E - 1);
        const float4* ar = (const float4*)(edge_attr + (size_t)ec * ED + cb);
        float v[16];
        float s = 0.f, qs = 0.f;
        #pragma unroll
        for (int q = 0; q < 4; q++) {
            float4 d = *(const float4*)(buf + r * 68 + cb + q * 4);
            float4 a = ar[q];
            v[q*4+0] = a.x + d.x; v[q*4+1] = a.y + d.y;
            v[q*4+2] = a.z + d.z; v[q*4+3] = a.w + d.w;
            s  += v[q*4+0] + v[q*4+1] + v[q*4+2] + v[q*4+3];
            qs += v[q*4+0]*v[q*4+0] + v[q*4+1]*v[q*4+1]
                + v[q*4+2]*v[q*4+2] + v[q*4+3]*v[q*4+3];
        }
        s  += __shfl_xor_sync(0xffffffffu, s, 1);  qs += __shfl_xor_sync(0xffffffffu, qs, 1);
        s  += __shfl_xor_sync(0xffffffffu, s, 2);  qs += __shfl_xor_sync(0xffffffffu, qs, 2);
        float mean = s * 0.015625f;
        float var  = qs * 0.015625f - mean * mean;
        float inv  = rsqrtf(var + 1e-5f);
        if (e < E) {
            float4* op = (float4*)(out + (size_t)e * ED + cb);
            #pragma unroll
            for (int q = 0; q < 4; q++) {
                int c = cb + q * 4;
                float4 o;
                o.x = (v[q*4+0] - mean) * inv * __ldg(ln_w + c)     + __ldg(ln_b + c);
                o.y = (v[q*4+1] - mean) * inv * __ldg(ln_w + c + 1) + __ldg(ln_b + c + 1);
                o.z = (v[q*4+2] - mean) * inv * __ldg(ln_w + c + 2) + __ldg(ln_b + c + 2);
                o.w = (v[q*4+3] - mean) * inv * __ldg(ln_w + c + 3) + __ldg(ln_b + c + 3);
                op[q] = o;
            }
        }
    }
}

extern "C" void kernel_launch(void* const* d_in, const int* in_sizes, int n_in,
                              void* d_out, int out_size) {
    const float* x   = (const float*)d_in[0];
    const int*   ei  = (const int*)d_in[1];
    const float* ea  = (const float*)d_in[2];
    const float* w1  = (const float*)d_in[3];
    const float* b1  = (const float*)d_in[4];
    const float* w2  = (const float*)d_in[5];
    const float* b2  = (const float*)d_in[6];
    const float* lnw = (const float*)d_in[7];
    const float* lnb = (const float*)d_in[8];
    float* out = (float*)d_out;

    int E = in_sizes[1] / 2;
    int N = in_sizes[0] / ND;

    static int init_done = 0;
    int smem_pre = (TM * ND + TM * HID) * (int)sizeof(float);   // 98304
    if (!init_done) {
        cudaFuncSetAttribute(precompute_kernel,
                             cudaFuncAttributeMaxDynamicSharedMemorySize, smem_pre);
        cudaFuncSetAttribute(edge_tc_kernel,
                             cudaFuncAttributeMaxDynamicSharedMemorySize, EDGE_SMEM);
        init_done = 1;
    }

    prep_weights<<<(64 * HID + HID * ED + 255) / 256, 256>>>(w1, w2);

    dim3 pgrid((N + TM - 1) / TM, 2);
    precompute_kernel<<<pgrid, NTHREADS, smem_pre>>>(x, w1, b1, N);

    int egrid = (E + TM - 1) / TM;
    edge_tc_kernel<<<egrid, NTHREADS, EDGE_SMEM>>>(
        ei, ea, b2, lnw, lnb, out, E, N);
}

// round 8
// speedup vs baseline: 1.1697x; 1.0362x over previous
#include <cuda_runtime.h>
#include <cstdint>

#define ND 128
#define ED 64
#define HID 256
#define NMAX 100000
#define TM 64          // rows per CTA
#define NTHREADS 256

typedef unsigned long long ull;

__device__ __forceinline__ ull pack2(float lo, float hi) {
    ull r; asm("mov.b64 %0, {%1, %2};" : "=l"(r) : "f"(lo), "f"(hi)); return r;
}
__device__ __forceinline__ void fma2(ull &d, ull a, ull b) {
    asm("fma.rn.f32x2 %0, %1, %2, %0;" : "+l"(d) : "l"(a), "l"(b));
}
__device__ __forceinline__ ull add2(ull a, ull b) {
    ull r; asm("add.rn.f32x2 %0, %1, %2;" : "=l"(r) : "l"(a), "l"(b)); return r;
}
__device__ __forceinline__ float2 unpack2(ull v) {
    float2 f; asm("mov.b64 {%0, %1}, %2;" : "=f"(f.x), "=f"(f.y) : "l"(v)); return f;
}

// Per-node precomputed partials: Pa = x@W1a + b1, Pb = x@W1b
__device__ __align__(16) float g_Pa[(size_t)NMAX * HID];
__device__ __align__(16) float g_Pb[(size_t)NMAX * HID];
// W2 in k-pair block layout: [chunk 0..3][k4 0..15][col 0..63][4 floats]
// block (ch,k4,c) holds w2[ch*64 + k4*4 + q][c], q=0..3
__device__ __align__(16) float g_W2t4[4 * 16 * 64 * 4];

extern __shared__ float smem[];

// ===================== Prep: W2 -> 16B k-pair blocks ===========================
__global__ void prep_w2t4(const float* __restrict__ w2) {
    int i = blockIdx.x * blockDim.x + threadIdx.x;   // 16384
    if (i < 4 * 16 * 64 * 4) {
        int q  = i & 3;
        int c  = (i >> 2) & 63;
        int k4 = (i >> 8) & 15;
        int ch = i >> 12;
        g_W2t4[i] = w2[(size_t)(ch * 64 + k4 * 4 + q) * ED + c];
    }
}

// ===================== Kernel 1: node-level precompute (unchanged R5) ==========
__global__ __launch_bounds__(NTHREADS, 2) void precompute_kernel(
    const float* __restrict__ x,
    const float* __restrict__ w1, const float* __restrict__ b1, int N)
{
    float* Xs = smem;              // [64][128]
    float* Bs = smem + TM * ND;    // [64][256]

    const int tid = threadIdx.x;
    const int tx  = tid & 31;
    const int ty  = tid >> 5;
    const int r0  = ty * 8;
    const int m0  = blockIdx.x * TM;
    const int half = blockIdx.y;

    int node[8];
    #pragma unroll
    for (int r = 0; r < 8; r++) {
        node[r] = min(m0 + r0 + r, N - 1);
        ((float4*)(Xs + (r0 + r) * ND))[tx] =
            ((const float4*)(x + (size_t)node[r] * ND))[tx];
    }

    ull acc[8][4];
    if (half == 0) {
        ull bv[4];
        #pragma unroll
        for (int j = 0; j < 4; j++) {
            float2 b = ((const float2*)b1)[tx + 32 * j];
            bv[j] = pack2(b.x, b.y);
        }
        #pragma unroll
        for (int i = 0; i < 8; i++)
            #pragma unroll
            for (int j = 0; j < 4; j++) acc[i][j] = bv[j];
    } else {
        #pragma unroll
        for (int i = 0; i < 8; i++)
            #pragma unroll
            for (int j = 0; j < 4; j++) acc[i][j] = 0ull;
    }

    for (int kt = 0; kt < ND; kt += 64) {
        __syncthreads();
        const float4* wf4 = (const float4*)(w1 + (size_t)(half * ND + kt) * HID);
        #pragma unroll
        for (int it = 0; it < 16; it++) {
            int q = tid + it * NTHREADS;
            ((float4*)Bs)[q] = wf4[q];
        }
        __syncthreads();
        #pragma unroll 4
        for (int kk4 = 0; kk4 < 64; kk4 += 4) {
            float4 a4[8];
            #pragma unroll
            for (int i = 0; i < 8; i++)
                a4[i] = *(const float4*)(Xs + (r0 + i) * ND + kt + kk4);
            #pragma unroll
            for (int kq = 0; kq < 4; kq++) {
                const ull* Br = (const ull*)(Bs + (kk4 + kq) * HID) + tx;
                ull b0 = Br[0], b1r = Br[32], b2r = Br[64], b3r = Br[96];
                #pragma unroll
                for (int i = 0; i < 8; i++) {
                    float a = (&a4[i].x)[kq];
                    ull aa = pack2(a, a);
                    fma2(acc[i][0], aa, b0);
                    fma2(acc[i][1], aa, b1r);
                    fma2(acc[i][2], aa, b2r);
                    fma2(acc[i][3], aa, b3r);
                }
            }
        }
    }

    float* P = half ? g_Pb : g_Pa;
    #pragma unroll
    for (int i = 0; i < 8; i++) {
        float2* dst = (float2*)(P + (size_t)node[i] * HID);
        #pragma unroll
        for (int j = 0; j < 4; j++)
            dst[tx + 32 * j] = unpack2(acc[i][j]);
    }
}

// ===================== Kernel 2: per-edge fused MLP + LN ========================
// SMEM: Es [64][64] | Ws [64][256] (W1c then h) | Cs [16][64][4] (W2 chunk)
__global__ __launch_bounds__(NTHREADS, 2) void edge_kernel(
    const int* __restrict__ ei32,
    const float* __restrict__ edge_attr,
    const float* __restrict__ w1,       // rows [256,320) = W1c
    const float* __restrict__ w2_unused, const float* __restrict__ b2,
    const float* __restrict__ ln_w, const float* __restrict__ ln_b,
    float* __restrict__ out, int E, int N)
{
    float* Es = smem;                       // 16 KB
    float* Ws = smem + TM * ED;             // 64 KB
    float* Cs = smem + TM * ED + TM * HID;  // 16 KB

    const int tid = threadIdx.x;
    const int tx  = tid & 31;
    const int ty  = tid >> 5;
    const int r0  = ty * 8;
    const int e0  = blockIdx.x * TM;

    // int64/int32 detection
    unsigned oddbits = 0;
    #pragma unroll
    for (int k = 0; k < 16; k++) oddbits |= (unsigned)ei32[2 * k + 1];
    const int step = (oddbits == 0) ? 2 : 1;

    // W1c tile: w1 rows [256,320) -> Ws [64][256]
    {
        const float4* wf4 = (const float4*)(w1 + (size_t)(2 * ND) * HID);
        #pragma unroll
        for (int it = 0; it < 16; it++) {
            int q = tid + it * NTHREADS;
            ((float4*)Ws)[q] = wf4[q];
        }
    }

    // per-row: load edge_attr into Es; init acc = Pa[dst] + Pb[src]
    ull acc[8][4];
    #pragma unroll
    for (int r = 0; r < 8; r++) {
        int e = min(e0 + r0 + r, E - 1);
        int ss = ei32[(size_t)step * e];
        int ds = ei32[(size_t)step * (E + e)];
        ss = min(max(ss, 0), N - 1);
        ds = min(max(ds, 0), N - 1);
        if (tx < 16)
            ((float4*)(Es + (r0 + r) * ED))[tx] =
                ((const float4*)(edge_attr + (size_t)e * ED))[tx];
        const ull* pa = (const ull*)(g_Pa + (size_t)ds * HID) + tx;
        const ull* pb = (const ull*)(g_Pb + (size_t)ss * HID) + tx;
        #pragma unroll
        for (int j = 0; j < 4; j++)
            acc[r][j] = add2(pa[32 * j], pb[32 * j]);
    }
    __syncthreads();   // Ws (W1c) + Es visible

    // -------- GEMM1 remainder: acc += ea @ W1c  (K = 64) --------
    #pragma unroll 4
    for (int kk4 = 0; kk4 < ED; kk4 += 4) {
        float4 a4[8];
        #pragma unroll
        for (int i = 0; i < 8; i++)
            a4[i] = *(const float4*)(Es + (r0 + i) * ED + kk4);
        #pragma unroll
        for (int kq = 0; kq < 4; kq++) {
            const ull* Br = (const ull*)(Ws + (kk4 + kq) * HID) + tx;
            ull b0 = Br[0], b1r = Br[32], b2r = Br[64], b3r = Br[96];
            #pragma unroll
            for (int i = 0; i < 8; i++) {
                float a = (&a4[i].x)[kq];
                ull aa = pack2(a, a);
                fma2(acc[i][0], aa, b0);
                fma2(acc[i][1], aa, b1r);
                fma2(acc[i][2], aa, b2r);
                fma2(acc[i][3], aa, b3r);
            }
        }
    }
    __syncthreads();   // all W1c reads done; Ws becomes h

    // h = relu(acc) -> Ws (own rows; conflict-free float2 stores)
    #pragma unroll
    for (int i = 0; i < 8; i++) {
        float* hr = Ws + (r0 + i) * HID;
        #pragma unroll
        for (int j = 0; j < 4; j++) {
            float2 v = unpack2(acc[i][j]);
            v.x = fmaxf(v.x, 0.f);
            v.y = fmaxf(v.y, 0.f);
            ((float2*)hr)[tx + 32 * j] = v;
        }
    }

    // -------- GEMM2: delta = h @ W2, k-pair packed (no packing MOVs) --------
    // acc2[i][j]: (even-k, odd-k) partial sums for row r0+i, col tx+32j
    ull acc2[8][2];
    #pragma unroll
    for (int i = 0; i < 8; i++) { acc2[i][0] = 0ull; acc2[i][1] = 0ull; }

    for (int ch = 0; ch < 4; ch++) {
        __syncthreads();   // prev Cs reads done (h stores are own-warp rows)
        {
            const float4* src = (const float4*)(g_W2t4 + ch * 4096);
            float4* dst = (float4*)Cs;
            #pragma unroll
            for (int it = 0; it < 4; it++) {
                int q = tid + it * NTHREADS;   // 1024 float4
                dst[q] = src[q];
            }
        }
        __syncthreads();
        #pragma unroll 4
        for (int k4 = 0; k4 < 16; k4++) {
            // B: blocks (k4, tx) and (k4, tx+32), consecutive 16B -> conflict-free
            ulonglong2 bA = *(const ulonglong2*)(Cs + (k4 * 64 + tx) * 4);
            ulonglong2 bB = *(const ulonglong2*)(Cs + (k4 * 64 + tx + 32) * 4);
            #pragma unroll
            for (int i = 0; i < 8; i++) {
                // A: h[row][4k] broadcast, pairs land directly in reg pairs
                ulonglong2 ha = *(const ulonglong2*)(Ws + (r0 + i) * HID + ch * 64 + k4 * 4);
                fma2(acc2[i][0], ha.x, bA.x);
                fma2(acc2[i][0], ha.y, bA.y);
                fma2(acc2[i][1], ha.x, bB.x);
                fma2(acc2[i][1], ha.y, bB.y);
            }
        }
    }

    // -------- Epilogue: residual + LayerNorm(64) + affine --------
    float b2a = __ldg(b2 + tx),   b2b = __ldg(b2 + tx + 32);
    float lwa = __ldg(ln_w + tx), lwb = __ldg(ln_w + tx + 32);
    float lba = __ldg(ln_b + tx), lbb = __ldg(ln_b + tx + 32);

    #pragma unroll
    for (int i = 0; i < 8; i++) {
        float2 p0 = unpack2(acc2[i][0]);
        float2 p1 = unpack2(acc2[i][1]);
        float d0 = p0.x + p0.y;        // even + odd partial sums
        float d1 = p1.x + p1.y;
        float v0 = Es[(r0 + i) * ED + tx]      + d0 + b2a;
        float v1 = Es[(r0 + i) * ED + tx + 32] + d1 + b2b;
        float s = v0 + v1;
        float q = v0 * v0 + v1 * v1;
        #pragma unroll
        for (int off = 16; off > 0; off >>= 1) {
            s += __shfl_xor_sync(0xffffffffu, s, off);
            q += __shfl_xor_sync(0xffffffffu, q, off);
        }
        float mean = s * 0.015625f;
        float var  = q * 0.015625f - mean * mean;
        float inv  = rsqrtf(var + 1e-5f);
        int e = e0 + r0 + i;
        if (e < E) {
            float* op = out + (size_t)e * ED;
            op[tx]      = (v0 - mean) * inv * lwa + lba;
            op[tx + 32] = (v1 - mean) * inv * lwb + lbb;
        }
    }
}

extern "C" void kernel_launch(void* const* d_in, const int* in_sizes, int n_in,
                              void* d_out, int out_size) {
    const float* x   = (const float*)d_in[0];
    const int*   ei  = (const int*)d_in[1];
    const float* ea  = (const float*)d_in[2];
    const float* w1  = (const float*)d_in[3];
    const float* b1  = (const float*)d_in[4];
    const float* w2  = (const float*)d_in[5];
    const float* b2  = (const float*)d_in[6];
    const float* lnw = (const float*)d_in[7];
    const float* lnb = (const float*)d_in[8];
    float* out = (float*)d_out;

    int E = in_sizes[1] / 2;
    int N = in_sizes[0] / ND;

    static int init_done = 0;
    int smem_pre  = (TM * ND + TM * HID) * (int)sizeof(float);            // 98304
    int smem_edge = (TM * ED + TM * HID + 16 * 64 * 4) * (int)sizeof(float); // 98304
    if (!init_done) {
        cudaFuncSetAttribute(precompute_kernel,
                             cudaFuncAttributeMaxDynamicSharedMemorySize, smem_pre);
        cudaFuncSetAttribute(edge_kernel,
                             cudaFuncAttributeMaxDynamicSharedMemorySize, smem_edge);
        init_done = 1;
    }

    prep_w2t4<<<64, 256>>>(w2);

    dim3 pgrid((N + TM - 1) / TM, 2);
    precompute_kernel<<<pgrid, NTHREADS, smem_pre>>>(x, w1, b1, N);

    int egrid = (E + TM - 1) / TM;
    edge_kernel<<<egrid, NTHREADS, smem_edge>>>(
        ei, ea, w1, w2, b2, lnw, lnb, out, E, N);
}

// round 9
// speedup vs baseline: 1.2038x; 1.0291x over previous
#include <cuda_runtime.h>
#include <cstdint>

#define ND 128
#define ED 64
#define HID 256
#define NMAX 100000
#define TM 64
#define NTHREADS 256

typedef unsigned long long ull;

__device__ __forceinline__ ull pack2(float lo, float hi) {
    ull r; asm("mov.b64 %0, {%1, %2};" : "=l"(r) : "f"(lo), "f"(hi)); return r;
}
__device__ __forceinline__ void fma2(ull &d, ull a, ull b) {
    asm("fma.rn.f32x2 %0, %1, %2, %0;" : "+l"(d) : "l"(a), "l"(b));
}
__device__ __forceinline__ ull add2(ull a, ull b) {
    ull r; asm("add.rn.f32x2 %0, %1, %2;" : "=l"(r) : "l"(a), "l"(b)); return r;
}
__device__ __forceinline__ float2 unpack2(ull v) {
    float2 f; asm("mov.b64 {%0, %1}, %2;" : "=f"(f.x), "=f"(f.y) : "l"(v)); return f;
}

// Per-node precomputed partials: Pa = x@W1a + b1, Pb = x@W1b
__device__ __align__(16) float g_Pa[(size_t)NMAX * HID];
__device__ __align__(16) float g_Pb[(size_t)NMAX * HID];

extern __shared__ float smem[];

// ============ Kernel 1: node precompute, both halves in one pass ===============
__global__ __launch_bounds__(NTHREADS, 2) void precompute_kernel(
    const float* __restrict__ x,
    const float* __restrict__ w1, const float* __restrict__ b1, int N)
{
    float* Xs = smem;              // [64][128] 32 KB
    float* Bs = smem + TM * ND;    // [64][256] 64 KB

    const int tid = threadIdx.x;
    const int tx  = tid & 31;
    const int ty  = tid >> 5;
    const int r0  = ty * 8;
    const int m0  = blockIdx.x * TM;

    int node[8];
    #pragma unroll
    for (int r = 0; r < 8; r++) {
        node[r] = min(m0 + r0 + r, N - 1);
        ((float4*)(Xs + (r0 + r) * ND))[tx] =
            ((const float4*)(x + (size_t)node[r] * ND))[tx];
    }

    for (int half = 0; half < 2; half++) {
        ull acc[8][4];
        if (half == 0) {
            ull bv[4];
            #pragma unroll
            for (int j = 0; j < 4; j++) {
                float2 b = ((const float2*)b1)[tx + 32 * j];
                bv[j] = pack2(b.x, b.y);
            }
            #pragma unroll
            for (int i = 0; i < 8; i++)
                #pragma unroll
                for (int j = 0; j < 4; j++) acc[i][j] = bv[j];
        } else {
            #pragma unroll
            for (int i = 0; i < 8; i++)
                #pragma unroll
                for (int j = 0; j < 4; j++) acc[i][j] = 0ull;
        }

        for (int kt = 0; kt < ND; kt += 64) {
            __syncthreads();
            const float4* wf4 = (const float4*)(w1 + (size_t)(half * ND + kt) * HID);
            #pragma unroll
            for (int it = 0; it < 16; it++) {
                int q = tid + it * NTHREADS;
                ((float4*)Bs)[q] = wf4[q];
            }
            __syncthreads();
            #pragma unroll 4
            for (int kk4 = 0; kk4 < 64; kk4 += 4) {
                float4 a4[8];
                #pragma unroll
                for (int i = 0; i < 8; i++)
                    a4[i] = *(const float4*)(Xs + (r0 + i) * ND + kt + kk4);
                #pragma unroll
                for (int kq = 0; kq < 4; kq++) {
                    const ull* Br = (const ull*)(Bs + (kk4 + kq) * HID) + tx;
                    ull b0 = Br[0], b1r = Br[32], b2r = Br[64], b3r = Br[96];
                    #pragma unroll
                    for (int i = 0; i < 8; i++) {
                        float a = (&a4[i].x)[kq];
                        ull aa = pack2(a, a);
                        fma2(acc[i][0], aa, b0);
                        fma2(acc[i][1], aa, b1r);
                        fma2(acc[i][2], aa, b2r);
                        fma2(acc[i][3], aa, b3r);
                    }
                }
            }
        }

        float* P = half ? g_Pb : g_Pa;
        #pragma unroll
        for (int i = 0; i < 8; i++) {
            float2* dst = (float2*)(P + (size_t)node[i] * HID);
            #pragma unroll
            for (int j = 0; j < 4; j++)
                dst[tx + 32 * j] = unpack2(acc[i][j]);
        }
    }
}

// ===================== Kernel 2: per-edge fused MLP + LN ========================
// SMEM: Es [64][64] (ea, then W2 chunks for kh=1, then kh=1 partials) 16 KB
//       Ws [64][256] (W1c, then h) 64 KB
//       Cs [64][64] (W2 chunks for kh=0, then kh=0 partials) 16 KB
#define EDGE_SMEM ((TM * ED + TM * HID + TM * ED) * 4)   // 98304 B

__global__ __launch_bounds__(NTHREADS, 2) void edge_kernel(
    const int* __restrict__ ei32,
    const float* __restrict__ edge_attr,
    const float* __restrict__ w1,       // rows [256,320) = W1c
    const float* __restrict__ w2, const float* __restrict__ b2,
    const float* __restrict__ ln_w, const float* __restrict__ ln_b,
    float* __restrict__ out, int E, int N)
{
    float* Es = smem;
    float* Ws = smem + TM * ED;
    float* Cs = smem + TM * ED + TM * HID;

    const int tid = threadIdx.x;
    const int tx  = tid & 31;
    const int w   = tid >> 5;           // warp 0..7
    const int r0  = w * 8;              // GEMM1/epilogue rows
    const int rg  = w & 3;              // GEMM2 row group (16 rows)
    const int kh  = w >> 2;             // GEMM2 k half
    const int R2  = rg * 16;
    const int e0  = blockIdx.x * TM;

    // int64/int32 detection
    unsigned oddbits = 0;
    #pragma unroll
    for (int k = 0; k < 16; k++) oddbits |= (unsigned)ei32[2 * k + 1];
    const int step = (oddbits == 0) ? 2 : 1;

    // W1c tile -> Ws [64][256]
    {
        const float4* wf4 = (const float4*)(w1 + (size_t)(2 * ND) * HID);
        #pragma unroll
        for (int it = 0; it < 16; it++) {
            int q = tid + it * NTHREADS;
            ((float4*)Ws)[q] = wf4[q];
        }
    }

    // per-row: ea -> Es; acc = Pa[dst] + Pb[src]
    ull acc[8][4];
    #pragma unroll
    for (int r = 0; r < 8; r++) {
        int e = min(e0 + r0 + r, E - 1);
        int ss = ei32[(size_t)step * e];
        int ds = ei32[(size_t)step * (E + e)];
        ss = min(max(ss, 0), N - 1);
        ds = min(max(ds, 0), N - 1);
        if (tx < 16)
            ((float4*)(Es + (r0 + r) * ED))[tx] =
                ((const float4*)(edge_attr + (size_t)e * ED))[tx];
        const ull* pa = (const ull*)(g_Pa + (size_t)ds * HID) + tx;
        const ull* pb = (const ull*)(g_Pb + (size_t)ss * HID) + tx;
        #pragma unroll
        for (int j = 0; j < 4; j++)
            acc[r][j] = add2(pa[32 * j], pb[32 * j]);
    }
    __syncthreads();

    // -------- GEMM1 remainder: acc += ea @ W1c (K = 64) --------
    #pragma unroll 4
    for (int kk4 = 0; kk4 < ED; kk4 += 4) {
        float4 a4[8];
        #pragma unroll
        for (int i = 0; i < 8; i++)
            a4[i] = *(const float4*)(Es + (r0 + i) * ED + kk4);
        #pragma unroll
        for (int kq = 0; kq < 4; kq++) {
            const ull* Br = (const ull*)(Ws + (kk4 + kq) * HID) + tx;
            ull b0 = Br[0], b1r = Br[32], b2r = Br[64], b3r = Br[96];
            #pragma unroll
            for (int i = 0; i < 8; i++) {
                float a = (&a4[i].x)[kq];
                ull aa = pack2(a, a);
                fma2(acc[i][0], aa, b0);
                fma2(acc[i][1], aa, b1r);
                fma2(acc[i][2], aa, b2r);
                fma2(acc[i][3], aa, b3r);
            }
        }
    }
    __syncthreads();   // W1c + ea reads done; Ws -> h, Es -> W2/partials

    // h = relu(acc) -> Ws (own rows)
    #pragma unroll
    for (int i = 0; i < 8; i++) {
        float* hr = Ws + (r0 + i) * HID;
        #pragma unroll
        for (int j = 0; j < 4; j++) {
            float2 v = unpack2(acc[i][j]);
            v.x = fmaxf(v.x, 0.f);
            v.y = fmaxf(v.y, 0.f);
            ((float2*)hr)[tx + 32 * j] = v;
        }
    }

    // -------- GEMM2 split-k: warp (rg, kh) does rows [16rg,+16), k [128kh,+128) ----
    ull acc2[16];
    #pragma unroll
    for (int i = 0; i < 16; i++) acc2[i] = 0ull;

    for (int it = 0; it < 2; it++) {
        __syncthreads();   // h stores + prev chunk reads done
        {   // stage chunk (64*it) -> Cs (for kh=0) and (64*(2+it)) -> Es (for kh=1)
            const float4* s0 = (const float4*)(w2 + (size_t)(64 * it) * ED);
            const float4* s1 = (const float4*)(w2 + (size_t)(64 * (2 + it)) * ED);
            #pragma unroll
            for (int q = 0; q < 4; q++) {
                int idx = tid + q * NTHREADS;    // 1024 float4 each
                ((float4*)Cs)[idx] = s0[idx];
                ((float4*)Es)[idx] = s1[idx];
            }
        }
        __syncthreads();
        const float* Cbuf = kh ? Es : Cs;
        const int kbase = kh * 128 + it * 64;
        #pragma unroll 4
        for (int kk4 = 0; kk4 < 64; kk4 += 4) {
            ull b[4];
            #pragma unroll
            for (int q = 0; q < 4; q++)
                b[q] = *((const ull*)(Cbuf + (kk4 + q) * ED) + tx);
            #pragma unroll
            for (int half = 0; half < 2; half++) {
                float4 a4[8];
                #pragma unroll
                for (int i = 0; i < 8; i++)
                    a4[i] = *(const float4*)(Ws + (R2 + half * 8 + i) * HID + kbase + kk4);
                #pragma unroll
                for (int q = 0; q < 4; q++) {
                    #pragma unroll
                    for (int i = 0; i < 8; i++) {
                        float a = (&a4[i].x)[q];
                        fma2(acc2[half * 8 + i], pack2(a, a), b[q]);
                    }
                }
            }
        }
    }

    // -------- exchange partials: kh=0 -> Cs, kh=1 -> Es --------
    __syncthreads();   // all W2 chunk reads done
    {
        float2* Pbuf = (float2*)(kh ? Es : Cs);
        #pragma unroll
        for (int i = 0; i < 16; i++)
            Pbuf[(R2 + i) * 32 + tx] = unpack2(acc2[i]);
    }
    __syncthreads();

    // -------- Epilogue: delta = part0 + part1; residual + LayerNorm --------
    float2 b2v = ((const float2*)b2)[tx];
    float2 lwv = ((const float2*)ln_w)[tx];
    float2 lbv = ((const float2*)ln_b)[tx];

    #pragma unroll
    for (int i = 0; i < 8; i++) {
        int r = r0 + i;
        int e = e0 + r;
        int ec = min(e, E - 1);
        float2 p0 = ((const float2*)Cs)[r * 32 + tx];
        float2 p1 = ((const float2*)Es)[r * 32 + tx];
        float2 ar = ((const float2*)(edge_attr + (size_t)ec * ED))[tx];
        float v0 = ar.x + p0.x + p1.x + b2v.x;
        float v1 = ar.y + p0.y + p1.y + b2v.y;
        float s = v0 + v1;
        float q = v0 * v0 + v1 * v1;
        #pragma unroll
        for (int off = 16; off > 0; off >>= 1) {
            s += __shfl_xor_sync(0xffffffffu, s, off);
            q += __shfl_xor_sync(0xffffffffu, q, off);
        }
        float mean = s * 0.015625f;
        float var  = q * 0.015625f - mean * mean;
        float inv  = rsqrtf(var + 1e-5f);
        if (e < E) {
            float2 o;
            o.x = (v0 - mean) * inv * lwv.x + lbv.x;
            o.y = (v1 - mean) * inv * lwv.y + lbv.y;
            ((float2*)(out + (size_t)e * ED))[tx] = o;
        }
    }
}

extern "C" void kernel_launch(void* const* d_in, const int* in_sizes, int n_in,
                              void* d_out, int out_size) {
    const float* x   = (const float*)d_in[0];
    const int*   ei  = (const int*)d_in[1];
    const float* ea  = (const float*)d_in[2];
    const float* w1  = (const float*)d_in[3];
    const float* b1  = (const float*)d_in[4];
    const float* w2  = (const float*)d_in[5];
    const float* b2  = (const float*)d_in[6];
    const float* lnw = (const float*)d_in[7];
    const float* lnb = (const float*)d_in[8];
    float* out = (float*)d_out;

    int E = in_sizes[1] / 2;
    int N = in_sizes[0] / ND;

    static int init_done = 0;
    int smem_pre = (TM * ND + TM * HID) * (int)sizeof(float);   // 98304
    if (!init_done) {
        cudaFuncSetAttribute(precompute_kernel,
                             cudaFuncAttributeMaxDynamicSharedMemorySize, smem_pre);
        cudaFuncSetAttribute(edge_kernel,
                             cudaFuncAttributeMaxDynamicSharedMemorySize, EDGE_SMEM);
        init_done = 1;
    }

    int pgrid = (N + TM - 1) / TM;
    precompute_kernel<<<pgrid, NTHREADS, smem_pre>>>(x, w1, b1, N);

    int egrid = (E + TM - 1) / TM;
    edge_kernel<<<egrid, NTHREADS, EDGE_SMEM>>>(
        ei, ea, w1, w2, b2, lnw, lnb, out, E, N);
}